// round 15
// baseline (speedup 1.0000x reference)
#include <cuda_runtime.h>
#include <cuda_fp16.h>
#include <cstdint>

// ---------------- problem constants ----------------
#define HH 128
#define WW 256
#define HW (HH*WW)          // 32768
#define CC 256
#define NSAMP (HW*9)        // 294912

// ---------------- static device scratch ----------------
__device__ __half g_XT[(size_t)HW*256];      // [pixel][256] fp16
__device__ int    g_idx[NSAMP];
__device__ __half g_W[(size_t)1024*256];     // rows 0-767 qkv, 768-1023 wo (fp16)
__device__ float  g_bqkv[3*CC];
__device__ __half g_QKVh[(size_t)HW*3*CC];   // [pixel][768] = Q|K|V  fp16
__device__ __half g_OUT[(size_t)HW*256];     // [pixel][256] fp16

// ---------------- helpers ----------------
__device__ __forceinline__ uint32_t smem_u32(const void* p) {
    uint32_t a;
    asm("{ .reg .u64 t; cvta.to.shared.u64 t, %1; cvt.u32.u64 %0, t; }" : "=r"(a) : "l"(p));
    return a;
}
#define LDSM_X4(r, a) \
    asm volatile("ldmatrix.sync.aligned.m8n8.x4.shared.b16 {%0,%1,%2,%3}, [%4];" \
        : "=r"((r)[0]), "=r"((r)[1]), "=r"((r)[2]), "=r"((r)[3]) : "r"(a))

#define MMA16816(d, a, b) \
    asm volatile("mma.sync.aligned.m16n8k16.row.col.f32.f16.f16.f32 " \
        "{%0,%1,%2,%3}, {%4,%5,%6,%7}, {%8,%9}, {%0,%1,%2,%3};" \
        : "+f"((d)[0]), "+f"((d)[1]), "+f"((d)[2]), "+f"((d)[3]) \
        : "r"((a)[0]), "r"((a)[1]), "r"((a)[2]), "r"((a)[3]), "r"((b)[0]), "r"((b)[1]))

#define CP16(dst, src) \
    asm volatile("cp.async.cg.shared.global [%0], [%1], 16;" :: "r"(dst), "l"(src))
#define CP_COMMIT() asm volatile("cp.async.commit_group;")
#define CP_WAIT1()  asm volatile("cp.async.wait_group 1;")
#define CP_WAIT0()  asm volatile("cp.async.wait_group 0;")

// SMEM: 3 stages x 2 planes(128x80B)   (k-chunk = 32 halves = 64B data per row)
#define LDS_ROW 80
#define PL      (128*LDS_ROW)        // 10240 per plane
#define STG_SZ  (2*PL)               // 20480 per stage
#define SMEM_SZ (3*STG_SZ)           // 61440

// ---------------- index computation ----------------
__global__ void idx_kernel(const float* __restrict__ grid, int* __restrict__ idx)
{
    int s = blockIdx.x * 256 + threadIdx.x;
    if (s >= NSAMP) return;
    int p  = s / 9;
    int t  = s - p * 9;
    int h  = p >> 8;
    int w  = p & 255;
    int kh = t / 3;
    int kw = t - kh * 3;
    const float* g = grid + ((size_t)(h * 3 + kh) * 768 + (w * 3 + kw)) * 2;
    float fx = rintf(((g[0] + 1.0f) * 0.5f) * 255.0f);
    float fy = rintf(((g[1] + 1.0f) * 0.5f) * 127.0f);
    int ix = (int)fminf(fmaxf(fx, 0.0f), 255.0f);
    int iy = (int)fminf(fmaxf(fy, 0.0f), 127.0f);
    idx[s] = iy * WW + ix;
}

// ---------------- transpose x[C][HW] -> XT [HW][C] fp16 ----------------
__global__ void transpose_conv(const float* __restrict__ in, __half* __restrict__ o)
{
    __shared__ float tile[32][33];
    int c0 = blockIdx.x * 32;   // hw
    int r0 = blockIdx.y * 32;   // channel
    int tx = threadIdx.x, ty = threadIdx.y;
#pragma unroll
    for (int i = 0; i < 32; i += 8)
        tile[ty + i][tx] = in[(size_t)(r0 + ty + i) * HW + c0 + tx];
    __syncthreads();
#pragma unroll
    for (int i = 0; i < 32; i += 8)
        o[(size_t)(c0 + ty + i) * 256 + r0 + tx] = __float2half_rn(tile[tx][ty + i]);
}

// ---------------- fused weight/bias prep ----------------
__global__ void prep_weights(const float* __restrict__ wq, const float* __restrict__ wk,
                             const float* __restrict__ wv, const float* __restrict__ wo,
                             const float* __restrict__ bq, const float* __restrict__ bk,
                             const float* __restrict__ bv,
                             __half* __restrict__ W, float* __restrict__ bqkv)
{
    int i = blockIdx.x * 256 + threadIdx.x;
    if (i < 4 * CC * CC) {
        int m = i >> 16;
        int j = i & 0xFFFF;
        const float* src = (m == 0) ? wq : (m == 1) ? wk : (m == 2) ? wv : wo;
        W[i] = __float2half_rn(src[j]);
    } else {
        int j = i - 4 * CC * CC;
        if (j < 768)
            bqkv[j] = (j < 256) ? bq[j] : ((j < 512) ? bk[j - 256] : bv[j - 512]);
    }
}

// ---------------- HMMA fp16 GEMM: CTA 128x128, 4 warps of 64x64, 3-stage cp.async ----
// C[M][N] = A[M][256] * B[N][256]^T + bias.  128 threads, 2 CTAs/SM (256-reg budget).
// Per k16 step: 8 LDSM feed 32 independent MMAs (2x ILP vs 64x32 tiles).
template<bool ROWBIAS, bool HALFOUT>
__global__ __launch_bounds__(128, 2)
void hmma_gemm(const __half* __restrict__ A, const __half* __restrict__ B,
               const float* __restrict__ bias, void* __restrict__ Cv, int ldc)
{
    extern __shared__ __align__(16) char sm[];
    uint32_t smb = smem_u32(sm);
    int tid = threadIdx.x;
    int wid = tid >> 5, lane = tid & 31;
    int wm = wid >> 1, wn = wid & 1;         // 2x2 warp grid
    int m0 = blockIdx.y * 128, n0 = blockIdx.x * 128;

    // cp.async: one thread per row; 4x16B for A row chunk, 4x16B for B row chunk
    const char* srcA = (const char*)(A + (size_t)(m0 + tid) * 256);
    const char* srcB = (const char*)(B + (size_t)(n0 + tid) * 256);
    uint32_t dst = smb + tid * LDS_ROW;

    // ldmatrix fragment addresses (stage 0)
    uint32_t aAddr[4], bAddr[4];
#pragma unroll
    for (int mt = 0; mt < 4; mt++)
        aAddr[mt] = smb + (wm * 64 + mt * 16 + (lane & 15)) * LDS_ROW + ((lane >> 4) * 16);
#pragma unroll
    for (int bt = 0; bt < 4; bt++)
        bAddr[bt] = smb + PL + (wn * 64 + bt * 16 + ((lane >> 4) & 1) * 8 + (lane & 7)) * LDS_ROW
                  + (((lane >> 3) & 1) * 16);

    float acc[4][8][4];
#pragma unroll
    for (int i = 0; i < 4; i++)
#pragma unroll
        for (int j = 0; j < 8; j++)
#pragma unroll
            for (int k = 0; k < 4; k++) acc[i][j][k] = 0.0f;

    auto issue = [&](int ks, int stg) {
        uint32_t so = stg * STG_SZ;
        const char* sa = srcA + ks * 64;
        const char* sb = srcB + ks * 64;
#pragma unroll
        for (int c = 0; c < 4; c++) {
            CP16(dst + so + c * 16,      sa + c * 16);
            CP16(dst + so + PL + c * 16, sb + c * 16);
        }
    };

    issue(0, 0); CP_COMMIT();
    issue(1, 1); CP_COMMIT();

    int stg = 0;
#pragma unroll 1
    for (int ks = 0; ks < 8; ks++) {
        // drain schedule (verified): pending before wait = g_ks..g_{min(ks+1,7)};
        // need g_ks complete -> allowed outstanding = min(ks+1,7)-ks = 1 (ks<7), 0 (ks=7)
        if (ks < 7) { CP_WAIT1(); } else { CP_WAIT0(); }
        __syncthreads();
        if (ks < 6) { issue(ks + 2, (stg + 2) % 3); CP_COMMIT(); }
        uint32_t so = stg * STG_SZ;
#pragma unroll
        for (int kk = 0; kk < 2; kk++) {
            uint32_t ko = so + kk * 32;
            uint32_t a[4][4], b[4][4];
#pragma unroll
            for (int mt = 0; mt < 4; mt++) LDSM_X4(a[mt], aAddr[mt] + ko);
#pragma unroll
            for (int bt = 0; bt < 4; bt++) LDSM_X4(b[bt], bAddr[bt] + ko);
#pragma unroll
            for (int mt = 0; mt < 4; mt++)
#pragma unroll
                for (int nt = 0; nt < 8; nt++)
                    MMA16816(acc[mt][nt], a[mt], (&b[nt >> 1][(nt & 1) * 2]));
        }
        stg = (stg + 1) % 3;
    }

    // ---- epilogue ----
#pragma unroll
    for (int mt = 0; mt < 4; mt++) {
        int r0 = m0 + wm * 64 + mt * 16 + (lane >> 2);
        float rb0 = 0.f, rb1 = 0.f;
        if (ROWBIAS) { rb0 = bias[r0]; rb1 = bias[r0 + 8]; }
#pragma unroll
        for (int nt = 0; nt < 8; nt++) {
            int col = n0 + wn * 64 + nt * 8 + (lane & 3) * 2;
            float cb0 = 0.f, cb1 = 0.f;
            if (!ROWBIAS) { cb0 = bias[col]; cb1 = bias[col + 1]; }
            float v00 = acc[mt][nt][0] + (ROWBIAS ? rb0 : cb0);
            float v01 = acc[mt][nt][1] + (ROWBIAS ? rb0 : cb1);
            float v10 = acc[mt][nt][2] + (ROWBIAS ? rb1 : cb0);
            float v11 = acc[mt][nt][3] + (ROWBIAS ? rb1 : cb1);
            if (HALFOUT) {
                __half* C = (__half*)Cv;
                *(__half2*)(C + (size_t)r0 * ldc + col)       = __floats2half2_rn(v00, v01);
                *(__half2*)(C + (size_t)(r0 + 8) * ldc + col) = __floats2half2_rn(v10, v11);
            } else {
                float* C = (float*)Cv;
                *(float2*)(C + (size_t)r0 * ldc + col)       = make_float2(v00, v01);
                *(float2*)(C + (size_t)(r0 + 8) * ldc + col) = make_float2(v10, v11);
            }
        }
    }
}

// ---------------- attention v2: head-pair per warp, half2 lanes, 4-shuffle reduce ----------
__global__ __launch_bounds__(256)
void attn_kernel(const __half* __restrict__ QKV, const int* __restrict__ idx,
                 __half* __restrict__ OUT)
{
    int p0   = blockIdx.x << 6;        // 64 pixels per block
    int warp = threadIdx.x >> 5;
    int lane = threadIdx.x & 31;
    const float scale = 0.17677669529663687f;  // 1/sqrt(32)

#pragma unroll 1
    for (int task = warp; task < 256; task += 8) {
        int p  = task >> 2;
        int hp = task & 3;
        int pg = p0 + p;
        const int* ip = idx + pg * 9;
        int r[9];
#pragma unroll
        for (int t = 0; t < 9; t++) r[t] = ip[t];
        int cb = hp * 64 + 2 * lane;

        float2 qf = __half22float2(*(const __half2*)(QKV + (size_t)pg * 768 + cb));

        float part[9], vx[9], vy[9];
#pragma unroll
        for (int t = 0; t < 9; t++) {
            float2 kf = __half22float2(*(const __half2*)(QKV + (size_t)r[t] * 768 + 256 + cb));
            part[t] = qf.x * kf.x + qf.y * kf.y;
        }
#pragma unroll
        for (int t = 0; t < 9; t++) {
            float2 vf = __half22float2(*(const __half2*)(QKV + (size_t)r[t] * 768 + 512 + cb));
            vx[t] = vf.x; vy[t] = vf.y;
        }
#pragma unroll
        for (int t = 0; t < 9; t++) {
#pragma unroll
            for (int off = 8; off > 0; off >>= 1)
                part[t] += __shfl_xor_sync(0xffffffffu, part[t], off);
        }
        float lg[9];
#pragma unroll
        for (int t = 0; t < 9; t++) lg[t] = part[t] * scale;
        float mx = lg[0];
#pragma unroll
        for (int t = 1; t < 9; t++) mx = fmaxf(mx, lg[t]);
        float den = 0.0f, e[9];
#pragma unroll
        for (int t = 0; t < 9; t++) { e[t] = __expf(lg[t] - mx); den += e[t]; }
        float inv = 1.0f / den;
        float ox = 0.0f, oy = 0.0f;
#pragma unroll
        for (int t = 0; t < 9; t++) { ox += e[t] * vx[t]; oy += e[t] * vy[t]; }
        *(__half2*)(OUT + (size_t)pg * 256 + cb) = __floats2half2_rn(ox * inv, oy * inv);
    }
}

// ---------------- launch ----------------
extern "C" void kernel_launch(void* const* d_in, const int* in_sizes, int n_in,
                              void* d_out, int out_size)
{
    const float* x   = (const float*)d_in[0];
    const float* grd = (const float*)d_in[1];
    const float* wq  = (const float*)d_in[2];
    const float* bq  = (const float*)d_in[3];
    const float* wk  = (const float*)d_in[4];
    const float* bk  = (const float*)d_in[5];
    const float* wv  = (const float*)d_in[6];
    const float* bv  = (const float*)d_in[7];
    const float* wo  = (const float*)d_in[8];
    const float* bo  = (const float*)d_in[9];
    float* y = (float*)d_out;

    __half *XT, *W, *OUT, *QKVh;
    float *bqkv;
    int* idx;
    cudaGetSymbolAddress((void**)&XT,    g_XT);
    cudaGetSymbolAddress((void**)&idx,   g_idx);
    cudaGetSymbolAddress((void**)&W,     g_W);
    cudaGetSymbolAddress((void**)&QKVh,  g_QKVh);
    cudaGetSymbolAddress((void**)&bqkv,  g_bqkv);
    cudaGetSymbolAddress((void**)&OUT,   g_OUT);

    cudaFuncSetAttribute(hmma_gemm<false, true >, cudaFuncAttributeMaxDynamicSharedMemorySize, SMEM_SZ);
    cudaFuncSetAttribute(hmma_gemm<true,  false>, cudaFuncAttributeMaxDynamicSharedMemorySize, SMEM_SZ);

    // 1) gather indices
    idx_kernel<<<NSAMP / 256, 256>>>(grd, idx);

    // 2) x -> XT fp16; weights fp16 + bias concat
    transpose_conv<<<dim3(HW / 32, CC / 32), dim3(32, 8)>>>(x, XT);
    prep_weights<<<(4 * CC * CC + 768 + 255) / 256, 256>>>(
        wq, wk, wv, wo, bq, bk, bv, W, bqkv);

    // 3) fused QKV projection (single-pass fp16), fp16 out
    hmma_gemm<false, true><<<dim3(6, HW / 128), 128, SMEM_SZ>>>(
        XT, W, bqkv, QKVh, 768);

    // 4) attention v2 -> OUT fp16
    attn_kernel<<<HW / 64, 256>>>(QKVh, idx, OUT);

    // 5) y = wo * OUT^T + bo, fp32 out
    hmma_gemm<true, false><<<dim3(HW / 128, CC / 128), 128, SMEM_SZ>>>(
        W + (size_t)768 * 256, OUT, bo, y, HW);
}

// round 17
// speedup vs baseline: 1.1223x; 1.1223x over previous
#include <cuda_runtime.h>
#include <cuda_fp16.h>
#include <cstdint>

// ---------------- problem constants ----------------
#define HH 128
#define WW 256
#define HW (HH*WW)          // 32768
#define CC 256
#define NSAMP (HW*9)        // 294912

// ---------------- static device scratch ----------------
__device__ __half g_XT[(size_t)HW*256];      // [pixel][256] fp16
__device__ int    g_idx[NSAMP];
__device__ __half g_W[(size_t)1024*256];     // rows 0-767 qkv, 768-1023 wo (fp16)
__device__ float  g_bqkv[3*CC];
__device__ __half g_QKVh[(size_t)HW*3*CC];   // [pixel][768] = Q|K|V  fp16
__device__ __half g_OUT[(size_t)HW*256];     // [pixel][256] fp16

// ---------------- helpers ----------------
__device__ __forceinline__ uint32_t smem_u32(const void* p) {
    uint32_t a;
    asm("{ .reg .u64 t; cvta.to.shared.u64 t, %1; cvt.u32.u64 %0, t; }" : "=r"(a) : "l"(p));
    return a;
}
#define LDSM_X4(r, a) \
    asm volatile("ldmatrix.sync.aligned.m8n8.x4.shared.b16 {%0,%1,%2,%3}, [%4];" \
        : "=r"((r)[0]), "=r"((r)[1]), "=r"((r)[2]), "=r"((r)[3]) : "r"(a))

#define MMA16816(d, a, b) \
    asm volatile("mma.sync.aligned.m16n8k16.row.col.f32.f16.f16.f32 " \
        "{%0,%1,%2,%3}, {%4,%5,%6,%7}, {%8,%9}, {%0,%1,%2,%3};" \
        : "+f"((d)[0]), "+f"((d)[1]), "+f"((d)[2]), "+f"((d)[3]) \
        : "r"((a)[0]), "r"((a)[1]), "r"((a)[2]), "r"((a)[3]), "r"((b)[0]), "r"((b)[1]))

#define CP16(dst, src) \
    asm volatile("cp.async.cg.shared.global [%0], [%1], 16;" :: "r"(dst), "l"(src))
#define CP_COMMIT() asm volatile("cp.async.commit_group;")
#define CP_WAIT2()  asm volatile("cp.async.wait_group 2;")
#define CP_WAIT1()  asm volatile("cp.async.wait_group 1;")
#define CP_WAIT0()  asm volatile("cp.async.wait_group 0;")

// SMEM: 4 stages x 2 planes(128x80B)
#define LDS_ROW 80
#define PL      (128*LDS_ROW)        // 10240 per plane
#define STG_SZ  (2*PL)               // 20480 per stage
#define SMEM_SZ (4*STG_SZ)           // 81920

// ---------------- fused prep: transpose + idx + weights/bias in ONE launch -------------
// Block-partitioned flat grid:
//   blocks [0, 8192)          : transpose x[C][HW] -> XT [HW][C] fp16   (32x32 tiles)
//   blocks [8192, 9344)       : idx computation (1152 x 256 = 294912 = NSAMP)
//   blocks [9344, 9344+1027)  : weights fp16 + bias concat (1027 x 256 = 262912 needed)
#define NB_T   8192
#define NB_I   1152
#define NB_W   1027
__global__ __launch_bounds__(256)
void prep_all(const float* __restrict__ x, const float* __restrict__ grid,
              const float* __restrict__ wq, const float* __restrict__ wk,
              const float* __restrict__ wv, const float* __restrict__ wo,
              const float* __restrict__ bq, const float* __restrict__ bk,
              const float* __restrict__ bv,
              __half* __restrict__ XT, int* __restrict__ idx,
              __half* __restrict__ W, float* __restrict__ bqkv)
{
    int b = blockIdx.x;
    if (b < NB_T) {
        __shared__ float tile[32][33];
        int c0 = (b & 1023) * 32;          // hw
        int r0 = (b >> 10) * 32;           // channel
        int tx = threadIdx.x & 31, ty = threadIdx.x >> 5;
#pragma unroll
        for (int i = 0; i < 32; i += 8)
            tile[ty + i][tx] = x[(size_t)(r0 + ty + i) * HW + c0 + tx];
        __syncthreads();
#pragma unroll
        for (int i = 0; i < 32; i += 8)
            XT[(size_t)(c0 + ty + i) * 256 + r0 + tx] = __float2half_rn(tile[tx][ty + i]);
    } else if (b < NB_T + NB_I) {
        int s = (b - NB_T) * 256 + threadIdx.x;
        if (s >= NSAMP) return;
        int p  = s / 9;
        int t  = s - p * 9;
        int h  = p >> 8;
        int w  = p & 255;
        int kh = t / 3;
        int kw = t - kh * 3;
        const float* g = grid + ((size_t)(h * 3 + kh) * 768 + (w * 3 + kw)) * 2;
        float fx = rintf(((g[0] + 1.0f) * 0.5f) * 255.0f);
        float fy = rintf(((g[1] + 1.0f) * 0.5f) * 127.0f);
        int ix = (int)fminf(fmaxf(fx, 0.0f), 255.0f);
        int iy = (int)fminf(fmaxf(fy, 0.0f), 127.0f);
        idx[s] = iy * WW + ix;
    } else {
        int i = (b - NB_T - NB_I) * 256 + threadIdx.x;
        if (i < 4 * CC * CC) {
            int m = i >> 16;
            int j = i & 0xFFFF;
            const float* src = (m == 0) ? wq : (m == 1) ? wk : (m == 2) ? wv : wo;
            W[i] = __float2half_rn(src[j]);
        } else {
            int j = i - 4 * CC * CC;
            if (j < 768)
                bqkv[j] = (j < 256) ? bq[j] : ((j < 512) ? bk[j - 256] : bv[j - 512]);
        }
    }
}

// ---------------- HMMA fp16 single-pass GEMM, K=256, 4-stage cp.async (R13 exact) -------
template<bool ROWBIAS, bool HALFOUT>
__global__ __launch_bounds__(256, 2)
void hmma_gemm(const __half* __restrict__ A, const __half* __restrict__ B,
               const float* __restrict__ bias, void* __restrict__ Cv, int ldc)
{
    extern __shared__ __align__(16) char sm[];
    uint32_t smb = smem_u32(sm);
    int tid = threadIdx.x;
    int wid = tid >> 5, lane = tid & 31;
    int wm = wid >> 2, wn = wid & 3;
    int m0 = blockIdx.y * 128, n0 = blockIdx.x * 128;

    int row = tid >> 1, ch = (tid & 1) * 2;
    const char* srcA = (const char*)(A + (size_t)(m0 + row) * 256) + ch * 16;
    const char* srcB = (const char*)(B + (size_t)(n0 + row) * 256) + ch * 16;
    uint32_t dst = smb + row * LDS_ROW + ch * 16;

    uint32_t aAddr[4], bAddr[2];
#pragma unroll
    for (int mt = 0; mt < 4; mt++)
        aAddr[mt] = smb + (wm * 64 + mt * 16 + (lane & 15)) * LDS_ROW + ((lane >> 4) * 16);
#pragma unroll
    for (int bt = 0; bt < 2; bt++)
        bAddr[bt] = smb + PL + (wn * 32 + bt * 16 + ((lane >> 4) & 1) * 8 + (lane & 7)) * LDS_ROW
                  + (((lane >> 3) & 1) * 16);

    float acc[4][4][4];
#pragma unroll
    for (int i = 0; i < 4; i++)
#pragma unroll
        for (int j = 0; j < 4; j++)
#pragma unroll
            for (int k = 0; k < 4; k++) acc[i][j][k] = 0.0f;

    auto issue = [&](int ks, int stg) {
        uint32_t so = stg * STG_SZ;
#pragma unroll
        for (int c = 0; c < 2; c++) {
            CP16(dst + so + c * 16,      srcA + ks * 64 + c * 16);
            CP16(dst + so + PL + c * 16, srcB + ks * 64 + c * 16);
        }
    };

    issue(0, 0); CP_COMMIT();
    issue(1, 1); CP_COMMIT();
    issue(2, 2); CP_COMMIT();

#pragma unroll 1
    for (int ks = 0; ks < 8; ks++) {
        if (ks < 6)      { CP_WAIT2(); }
        else if (ks == 6){ CP_WAIT1(); }
        else             { CP_WAIT0(); }
        __syncthreads();
        if (ks < 5) { issue(ks + 3, (ks + 3) & 3); CP_COMMIT(); }
        uint32_t so = (ks & 3) * STG_SZ;
#pragma unroll
        for (int kk = 0; kk < 2; kk++) {
            uint32_t ko = so + kk * 32;
            uint32_t a[4][4], b[2][4];
#pragma unroll
            for (int mt = 0; mt < 4; mt++) LDSM_X4(a[mt], aAddr[mt] + ko);
#pragma unroll
            for (int bt = 0; bt < 2; bt++) LDSM_X4(b[bt], bAddr[bt] + ko);
#pragma unroll
            for (int mt = 0; mt < 4; mt++)
#pragma unroll
                for (int nt = 0; nt < 4; nt++)
                    MMA16816(acc[mt][nt], a[mt], (&b[nt >> 1][(nt & 1) * 2]));
        }
    }

    // ---- epilogue ----
#pragma unroll
    for (int mt = 0; mt < 4; mt++) {
        int r0 = m0 + wm * 64 + mt * 16 + (lane >> 2);
        float rb0 = 0.f, rb1 = 0.f;
        if (ROWBIAS) { rb0 = bias[r0]; rb1 = bias[r0 + 8]; }
#pragma unroll
        for (int nt = 0; nt < 4; nt++) {
            int col = n0 + wn * 32 + nt * 8 + (lane & 3) * 2;
            float cb0 = 0.f, cb1 = 0.f;
            if (!ROWBIAS) { cb0 = bias[col]; cb1 = bias[col + 1]; }
            float v00 = acc[mt][nt][0] + (ROWBIAS ? rb0 : cb0);
            float v01 = acc[mt][nt][1] + (ROWBIAS ? rb0 : cb1);
            float v10 = acc[mt][nt][2] + (ROWBIAS ? rb1 : cb0);
            float v11 = acc[mt][nt][3] + (ROWBIAS ? rb1 : cb1);
            if (HALFOUT) {
                __half* C = (__half*)Cv;
                *(__half2*)(C + (size_t)r0 * ldc + col)       = __floats2half2_rn(v00, v01);
                *(__half2*)(C + (size_t)(r0 + 8) * ldc + col) = __floats2half2_rn(v10, v11);
            } else {
                float* C = (float*)Cv;
                *(float2*)(C + (size_t)r0 * ldc + col)       = make_float2(v00, v01);
                *(float2*)(C + (size_t)(r0 + 8) * ldc + col) = make_float2(v10, v11);
            }
        }
    }
}

// ---------------- attention v2: head-pair per warp, half2 lanes, 4-shuffle reduce --------
__global__ __launch_bounds__(256)
void attn_kernel(const __half* __restrict__ QKV, const int* __restrict__ idx,
                 __half* __restrict__ OUT)
{
    int p0   = blockIdx.x << 6;        // 64 pixels per block
    int warp = threadIdx.x >> 5;
    int lane = threadIdx.x & 31;
    const float scale = 0.17677669529663687f;  // 1/sqrt(32)

#pragma unroll 1
    for (int task = warp; task < 256; task += 8) {
        int p  = task >> 2;
        int hp = task & 3;
        int pg = p0 + p;
        const int* ip = idx + pg * 9;
        int r[9];
#pragma unroll
        for (int t = 0; t < 9; t++) r[t] = ip[t];
        int cb = hp * 64 + 2 * lane;

        float2 qf = __half22float2(*(const __half2*)(QKV + (size_t)pg * 768 + cb));

        float part[9], vx[9], vy[9];
#pragma unroll
        for (int t = 0; t < 9; t++) {
            float2 kf = __half22float2(*(const __half2*)(QKV + (size_t)r[t] * 768 + 256 + cb));
            part[t] = qf.x * kf.x + qf.y * kf.y;
        }
#pragma unroll
        for (int t = 0; t < 9; t++) {
            float2 vf = __half22float2(*(const __half2*)(QKV + (size_t)r[t] * 768 + 512 + cb));
            vx[t] = vf.x; vy[t] = vf.y;
        }
#pragma unroll
        for (int t = 0; t < 9; t++) {
#pragma unroll
            for (int off = 8; off > 0; off >>= 1)
                part[t] += __shfl_xor_sync(0xffffffffu, part[t], off);
        }
        float lg[9];
#pragma unroll
        for (int t = 0; t < 9; t++) lg[t] = part[t] * scale;
        float mx = lg[0];
#pragma unroll
        for (int t = 1; t < 9; t++) mx = fmaxf(mx, lg[t]);
        float den = 0.0f, e[9];
#pragma unroll
        for (int t = 0; t < 9; t++) { e[t] = __expf(lg[t] - mx); den += e[t]; }
        float inv = 1.0f / den;
        float ox = 0.0f, oy = 0.0f;
#pragma unroll
        for (int t = 0; t < 9; t++) { ox += e[t] * vx[t]; oy += e[t] * vy[t]; }
        *(__half2*)(OUT + (size_t)pg * 256 + cb) = __floats2half2_rn(ox * inv, oy * inv);
    }
}

// ---------------- launch ----------------
extern "C" void kernel_launch(void* const* d_in, const int* in_sizes, int n_in,
                              void* d_out, int out_size)
{
    const float* x   = (const float*)d_in[0];
    const float* grd = (const float*)d_in[1];
    const float* wq  = (const float*)d_in[2];
    const float* bq  = (const float*)d_in[3];
    const float* wk  = (const float*)d_in[4];
    const float* bk  = (const float*)d_in[5];
    const float* wv  = (const float*)d_in[6];
    const float* bv  = (const float*)d_in[7];
    const float* wo  = (const float*)d_in[8];
    const float* bo  = (const float*)d_in[9];
    float* y = (float*)d_out;

    __half *XT, *W, *OUT, *QKVh;
    float *bqkv;
    int* idx;
    cudaGetSymbolAddress((void**)&XT,    g_XT);
    cudaGetSymbolAddress((void**)&idx,   g_idx);
    cudaGetSymbolAddress((void**)&W,     g_W);
    cudaGetSymbolAddress((void**)&QKVh,  g_QKVh);
    cudaGetSymbolAddress((void**)&bqkv,  g_bqkv);
    cudaGetSymbolAddress((void**)&OUT,   g_OUT);

    cudaFuncSetAttribute(hmma_gemm<false, true >, cudaFuncAttributeMaxDynamicSharedMemorySize, SMEM_SZ);
    cudaFuncSetAttribute(hmma_gemm<true,  false>, cudaFuncAttributeMaxDynamicSharedMemorySize, SMEM_SZ);

    // 1) fused prep: transpose + idx + weights/bias, single launch
    prep_all<<<NB_T + NB_I + NB_W, 256>>>(
        x, grd, wq, wk, wv, wo, bq, bk, bv, XT, idx, W, bqkv);

    // 2) fused QKV projection (single-pass fp16), fp16 out
    hmma_gemm<false, true><<<dim3(6, HW / 128), 256, SMEM_SZ>>>(
        XT, W, bqkv, QKVh, 768);

    // 3) attention v2 -> OUT fp16
    attn_kernel<<<HW / 64, 256>>>(QKVh, idx, OUT);

    // 4) y = wo * OUT^T + bo, fp32 out
    hmma_gemm<true, false><<<dim3(HW / 128, CC / 128), 256, SMEM_SZ>>>(
        W + (size_t)768 * 256, OUT, bo, y, HW);
}